// round 11
// baseline (speedup 1.0000x reference)
#include <cuda_runtime.h>

// Problem constants
#define Bb 4
#define Ff 5
#define Nn 2048
#define Dd 256
#define BFc (Bb*Ff)          // 20 frames
#define BFN (BFc*Nn)         // 40960
#define BFD (BFc*Dd)         // 5120
#define POSINF_BITS 0x7F800000

typedef unsigned long long u64;

// ---- scratch (no allocations allowed -> device globals) ----
__device__ int      g_rowmin[BFN];   // float bits, min over m of d[n,m]
__device__ int      g_colmin[BFN];   // float bits, min over n of d[n,m]
__device__ float    g_x2[BFN];
__device__ float    g_y2[BFN];
__device__ unsigned g_mnx[BFD], g_mxx[BFD], g_mny[BFD], g_mxy[BFD];
__device__ float    g_wx[Bb], g_wy[Bb];
__device__ float    g_sx[BFD], g_sy[BFD], g_of[BFD];

// monotonic unsigned encoding of float (total order incl. negatives)
__device__ __forceinline__ unsigned encf(float f) {
    unsigned u = __float_as_uint(f);
    return (u & 0x80000000u) ? ~u : (u | 0x80000000u);
}
__device__ __forceinline__ float decf(unsigned e) {
    unsigned u = (e & 0x80000000u) ? (e ^ 0x80000000u) : ~e;
    return __uint_as_float(u);
}

// packed f32x2 FMA: d = a*b + d (Blackwell dual-rate FP32 path)
#define FMA2(d, a, b) \
    asm("fma.rn.f32x2 %0, %1, %2, %0;" : "+l"(d) : "l"(a), "l"(b))

__device__ __forceinline__ float2 unpack2(u64 v) {
    float2 r;
    asm("mov.b64 {%0, %1}, %2;" : "=f"(r.x), "=f"(r.y) : "l"(v));
    return r;
}

// ---- reset accumulators (must run every launch: graph replays) ----
__global__ void k_init() {
    int i = blockIdx.x * blockDim.x + threadIdx.x;
    if (i < BFN) { g_rowmin[i] = POSINF_BITS; g_colmin[i] = POSINF_BITS; }
    if (i < BFD) {
        g_mnx[i] = 0xFFFFFFFFu; g_mny[i] = 0xFFFFFFFFu;
        g_mxx[i] = 0u;          g_mxy[i] = 0u;
    }
}

// ---- squared row norms: one warp per row, float4 loads ----
__global__ __launch_bounds__(256) void k_norms(const float* __restrict__ x,
                                               const float* __restrict__ y) {
    int row  = blockIdx.x * 8 + (threadIdx.x >> 5);
    int lane = threadIdx.x & 31;
    const float4* xr = (const float4*)(x + (size_t)row * Dd);
    const float4* yr = (const float4*)(y + (size_t)row * Dd);
    float sx = 0.f, sy = 0.f;
#pragma unroll
    for (int i = 0; i < 2; i++) {
        float4 v = xr[lane + 32 * i];
        sx += v.x * v.x + v.y * v.y + v.z * v.z + v.w * v.w;
        float4 w = yr[lane + 32 * i];
        sy += w.x * w.x + w.y * w.y + w.z * w.z + w.w * w.w;
    }
#pragma unroll
    for (int o = 16; o; o >>= 1) {
        sx += __shfl_xor_sync(0xFFFFFFFFu, sx, o);
        sy += __shfl_xor_sync(0xFFFFFFFFu, sy, o);
    }
    if (lane == 0) { g_x2[row] = sx; g_y2[row] = sy; }
}

// ---- tiled distance kernel: 128x128 tile, 8x8 per thread, packed f32x2 math
//      A tile stored DUPLICATED ({v,v}) so the broadcast operand is one LDS.64.
//      B columns blocked per thread (m = tx*8+j) so b-pairs are one LDS.64.
#define PA2 129   // As2 pad (float2 units) -> conflict-free stores
#define PAB 130   // Bs pad (floats), even -> 8B-aligned pair reads
__global__ __launch_bounds__(256) void k_dist(const float* __restrict__ x,
                                              const float* __restrict__ y) {
    const int bf = blockIdx.y;
    const int nt = blockIdx.x >> 4;
    const int mt = blockIdx.x & 15;
    const int n0 = nt * 128, m0 = mt * 128;
    const float* xb = x + (size_t)bf * Nn * Dd;
    const float* yb = y + (size_t)bf * Nn * Dd;

    __shared__ float2 As2[16][PA2];   // [k][n], value duplicated in both halves
    __shared__ float  Bs[16][PAB];    // [k][m]
    __shared__ int    s_row[128];
    __shared__ int    s_col[128];

    const int tid = threadIdx.x;
    const int tx = tid & 15, ty = tid >> 4;
    if (tid < 128) { s_row[tid] = POSINF_BITS; s_col[tid] = POSINF_BITS; }

    u64 acc[8][4];
#pragma unroll
    for (int i = 0; i < 8; i++)
#pragma unroll
        for (int j = 0; j < 4; j++) acc[i][j] = 0ull;

    const int lrow = tid >> 2;          // 0..63
    const int lk   = (tid & 3) << 2;    // 0,4,8,12

    for (int kc = 0; kc < Dd; kc += 16) {
        __syncthreads();   // protect smem from previous iteration's readers
#pragma unroll
        for (int r = 0; r < 2; r++) {
            int row = lrow + 64 * r;
            float4 v = *(const float4*)(xb + (size_t)(n0 + row) * Dd + kc + lk);
            As2[lk + 0][row] = make_float2(v.x, v.x);
            As2[lk + 1][row] = make_float2(v.y, v.y);
            As2[lk + 2][row] = make_float2(v.z, v.z);
            As2[lk + 3][row] = make_float2(v.w, v.w);
            float4 w = *(const float4*)(yb + (size_t)(m0 + row) * Dd + kc + lk);
            Bs[lk + 0][row] = w.x; Bs[lk + 1][row] = w.y;
            Bs[lk + 2][row] = w.z; Bs[lk + 3][row] = w.w;
        }
        __syncthreads();
#pragma unroll
        for (int k = 0; k < 16; k++) {
            u64 ap[8], bp[4];
#pragma unroll
            for (int i = 0; i < 8; i++)
                ap[i] = *(const u64*)&As2[k][ty + 16 * i];
#pragma unroll
            for (int jp = 0; jp < 4; jp++)
                bp[jp] = *(const u64*)&Bs[k][tx * 8 + 2 * jp];
#pragma unroll
            for (int i = 0; i < 8; i++)
#pragma unroll
                for (int jp = 0; jp < 4; jp++)
                    FMA2(acc[i][jp], ap[i], bp[jp]);
        }
    }

    // epilogue: d = x2 + y2 - 2*dot, fused row/col min
    const int nb = bf * Nn + n0, mb = bf * Nn + m0;
    float x2r[8], y2c[8];
#pragma unroll
    for (int i = 0; i < 8; i++) x2r[i] = g_x2[nb + ty + 16 * i];
#pragma unroll
    for (int j = 0; j < 8; j++) y2c[j] = g_y2[mb + tx * 8 + j];

    const float INFF = __int_as_float(POSINF_BITS);
    float cmin[8];
#pragma unroll
    for (int j = 0; j < 8; j++) cmin[j] = INFF;
#pragma unroll
    for (int i = 0; i < 8; i++) {
        float rm = INFF;
#pragma unroll
        for (int jp = 0; jp < 4; jp++) {
            float2 dot = unpack2(acc[i][jp]);
            float d0 = x2r[i] + y2c[2 * jp]     - 2.f * dot.x;
            float d1 = x2r[i] + y2c[2 * jp + 1] - 2.f * dot.y;
            rm = fminf(rm, fminf(d0, d1));
            cmin[2 * jp]     = fminf(cmin[2 * jp], d0);
            cmin[2 * jp + 1] = fminf(cmin[2 * jp + 1], d1);
        }
        atomicMin(&s_row[ty + 16 * i], __float_as_int(rm));
    }
#pragma unroll
    for (int j = 0; j < 8; j++)
        atomicMin(&s_col[tx * 8 + j], __float_as_int(cmin[j]));
    __syncthreads();
    if (tid < 128) {
        atomicMin(&g_rowmin[nb + tid], s_row[tid]);
        atomicMin(&g_colmin[mb + tid], s_col[tid]);
    }
}

// ---- reduce mins -> per-batch weights wx, wy ----
__global__ void k_wred() {
    int b = blockIdx.x;
    const int base = b * Ff * Nn;
    float sr = 0.f, sc = 0.f;
    for (int i = threadIdx.x; i < Ff * Nn; i += 256) {
        sr += __int_as_float(g_rowmin[base + i]);
        sc += __int_as_float(g_colmin[base + i]);
    }
    __shared__ float ssr[256], ssc[256];
    ssr[threadIdx.x] = sr; ssc[threadIdx.x] = sc;
    __syncthreads();
    for (int s = 128; s; s >>= 1) {
        if (threadIdx.x < s) {
            ssr[threadIdx.x] += ssr[threadIdx.x + s];
            ssc[threadIdx.x] += ssc[threadIdx.x + s];
        }
        __syncthreads();
    }
    if (threadIdx.x == 0) {
        g_wx[b] = 1.f / (1.f + ssr[0] / (float)(Ff * Nn));
        g_wy[b] = 1.f / (1.f + ssc[0] / (float)(Ff * Nn));
    }
}

// ---- per (bf,d) min/max over node dim, chunked over n ----
__global__ __launch_bounds__(256) void k_minmax(const float* __restrict__ x,
                                                const float* __restrict__ y) {
    int bf = blockIdx.x, c = blockIdx.y, d = threadIdx.x;
    const float* xp = x + ((size_t)bf * Nn + c * 128) * Dd + d;
    const float* yp = y + ((size_t)bf * Nn + c * 128) * Dd + d;
    const float INFF = __int_as_float(POSINF_BITS);
    float mnx = INFF, mxx = -INFF, mny = INFF, mxy = -INFF;
    for (int n = 0; n < 128; n++) {
        float vx = xp[(size_t)n * Dd];
        mnx = fminf(mnx, vx); mxx = fmaxf(mxx, vx);
        float vy = yp[(size_t)n * Dd];
        mny = fminf(mny, vy); mxy = fmaxf(mxy, vy);
    }
    int gi = bf * Dd + d;
    atomicMin(&g_mnx[gi], encf(mnx)); atomicMax(&g_mxx[gi], encf(mxx));
    atomicMin(&g_mny[gi], encf(mny)); atomicMax(&g_mxy[gi], encf(mxy));
}

// ---- fold weights + min/max into per-(bf,d) affine coefficients ----
__global__ void k_coef() {
    int i = blockIdx.x * blockDim.x + threadIdx.x;
    if (i >= BFD) return;
    int b = i / (Ff * Dd);
    float wx = g_wx[b], wy = g_wy[b];
    float mnx = decf(g_mnx[i]), mxx = decf(g_mxx[i]);
    float mny = decf(g_mny[i]), mxy = decf(g_mxy[i]);
    float sx = wx / (mxx - mnx);
    float sy = wy / (mxy - mny);
    g_sx[i] = sx; g_sy[i] = sy;
    g_of[i] = -mnx * sx - mny * sy;
}

// ---- final fused combine: out = x*sx + y*sy + off, float4 ----
__global__ __launch_bounds__(256) void k_combine(const float4* __restrict__ x,
                                                 const float4* __restrict__ y,
                                                 float4* __restrict__ out) {
    int idx = blockIdx.x * blockDim.x + threadIdx.x;
    const int total4 = Bb * Ff * Nn * Dd / 4;
    if (idx >= total4) return;
    int bf = idx / (Nn * Dd / 4);
    int d4 = idx & (Dd / 4 - 1);
    int ci = bf * (Dd / 4) + d4;
    float4 sx = ((const float4*)g_sx)[ci];
    float4 sy = ((const float4*)g_sy)[ci];
    float4 of = ((const float4*)g_of)[ci];
    float4 xv = x[idx], yv = y[idx];
    float4 o;
    o.x = fmaf(xv.x, sx.x, fmaf(yv.x, sy.x, of.x));
    o.y = fmaf(xv.y, sx.y, fmaf(yv.y, sy.y, of.y));
    o.z = fmaf(xv.z, sx.z, fmaf(yv.z, sy.z, of.z));
    o.w = fmaf(xv.w, sx.w, fmaf(yv.w, sy.w, of.w));
    out[idx] = o;
}

extern "C" void kernel_launch(void* const* d_in, const int* in_sizes, int n_in,
                              void* d_out, int out_size) {
    const float* x = (const float*)d_in[0];
    const float* y = (const float*)d_in[1];
    float* out = (float*)d_out;

    k_init<<<(BFN + 255) / 256, 256>>>();
    k_norms<<<BFN / 8, 256>>>(x, y);
    {
        dim3 gd(16 * 16, BFc);   // 256 tiles per frame, 20 frames
        k_dist<<<gd, 256>>>(x, y);
    }
    k_wred<<<Bb, 256>>>();
    {
        dim3 gm(BFc, Nn / 128);  // 20 frames x 16 n-chunks
        k_minmax<<<gm, 256>>>(x, y);
    }
    k_coef<<<(BFD + 255) / 256, 256>>>();
    {
        const int total4 = Bb * Ff * Nn * Dd / 4;
        k_combine<<<(total4 + 255) / 256, 256>>>((const float4*)x,
                                                 (const float4*)y,
                                                 (float4*)out);
    }
}

// round 12
// speedup vs baseline: 2.0594x; 2.0594x over previous
#include <cuda_runtime.h>

// Problem constants
#define Bb 4
#define Ff 5
#define Nn 2048
#define Dd 256
#define BFc (Bb*Ff)          // 20 frames
#define BFN (BFc*Nn)         // 40960
#define BFD (BFc*Dd)         // 5120
#define POSINF_BITS 0x7F800000

// ---- scratch (no allocations allowed -> device globals) ----
__device__ int      g_rowmin[BFN];   // float bits, min over m of d[n,m]
__device__ int      g_colmin[BFN];   // float bits, min over n of d[n,m]
__device__ float    g_x2[BFN];
__device__ float    g_y2[BFN];
__device__ unsigned g_mnx[BFD], g_mxx[BFD], g_mny[BFD], g_mxy[BFD];
__device__ float    g_wx[Bb], g_wy[Bb];
__device__ float    g_sx[BFD], g_sy[BFD], g_of[BFD];

// monotonic unsigned encoding of float (total order incl. negatives)
__device__ __forceinline__ unsigned encf(float f) {
    unsigned u = __float_as_uint(f);
    return (u & 0x80000000u) ? ~u : (u | 0x80000000u);
}
__device__ __forceinline__ float decf(unsigned e) {
    unsigned u = (e & 0x80000000u) ? (e ^ 0x80000000u) : ~e;
    return __uint_as_float(u);
}

__device__ __forceinline__ unsigned f2tf32(float f) {
    unsigned r;
    asm("cvt.rna.tf32.f32 %0, %1;" : "=r"(r) : "f"(f));
    return r;
}

// D(16x8,f32) += A(16x8,tf32,row) * B(8x8,tf32,col)
__device__ __forceinline__ void mma_tf32(float c[4],
                                         const unsigned a[4],
                                         const unsigned b[2]) {
    asm volatile(
        "mma.sync.aligned.m16n8k8.row.col.f32.tf32.tf32.f32 "
        "{%0,%1,%2,%3}, {%4,%5,%6,%7}, {%8,%9}, {%0,%1,%2,%3};"
        : "+f"(c[0]), "+f"(c[1]), "+f"(c[2]), "+f"(c[3])
        : "r"(a[0]), "r"(a[1]), "r"(a[2]), "r"(a[3]),
          "r"(b[0]), "r"(b[1]));
}

// ---- reset accumulators (must run every launch: graph replays) ----
__global__ void k_init() {
    int i = blockIdx.x * blockDim.x + threadIdx.x;
    if (i < BFN) { g_rowmin[i] = POSINF_BITS; g_colmin[i] = POSINF_BITS; }
    if (i < BFD) {
        g_mnx[i] = 0xFFFFFFFFu; g_mny[i] = 0xFFFFFFFFu;
        g_mxx[i] = 0u;          g_mxy[i] = 0u;
    }
}

// ---- squared row norms: one warp per row, float4 loads ----
__global__ __launch_bounds__(256) void k_norms(const float* __restrict__ x,
                                               const float* __restrict__ y) {
    int row  = blockIdx.x * 8 + (threadIdx.x >> 5);
    int lane = threadIdx.x & 31;
    const float4* xr = (const float4*)(x + (size_t)row * Dd);
    const float4* yr = (const float4*)(y + (size_t)row * Dd);
    float sx = 0.f, sy = 0.f;
#pragma unroll
    for (int i = 0; i < 2; i++) {
        float4 v = xr[lane + 32 * i];
        sx += v.x * v.x + v.y * v.y + v.z * v.z + v.w * v.w;
        float4 w = yr[lane + 32 * i];
        sy += w.x * w.x + w.y * w.y + w.z * w.z + w.w * w.w;
    }
#pragma unroll
    for (int o = 16; o; o >>= 1) {
        sx += __shfl_xor_sync(0xFFFFFFFFu, sx, o);
        sy += __shfl_xor_sync(0xFFFFFFFFu, sy, o);
    }
    if (lane == 0) { g_x2[row] = sx; g_y2[row] = sy; }
}

// ---- tensor-core distance kernel ----
// 128x128 CTA tile, 8 warps: warp = 32(n) x 64(m) = 2 x 8 m16n8k8 MMA tiles.
// Gram S = X . Y^T in tf32 (fp32 accum); epilogue fuses d = x2+y2-2S and
// row/col min reductions (shared atomics -> global atomics).
#define SKX 20   // smem row stride (16 k-values + 4 pad) -> conflict-free frags
__global__ __launch_bounds__(256, 1) void k_dist(const float* __restrict__ x,
                                                 const float* __restrict__ y) {
    const int bf = blockIdx.y;
    const int nt = blockIdx.x >> 4;
    const int mt = blockIdx.x & 15;
    const int n0 = nt * 128, m0 = mt * 128;
    const float* xb = x + (size_t)bf * Nn * Dd;
    const float* yb = y + (size_t)bf * Nn * Dd;

    __shared__ unsigned Xs[128 * SKX];   // tf32 bits, [n][k]
    __shared__ unsigned Ys[128 * SKX];   // tf32 bits, [m][k]
    __shared__ int s_row[128];
    __shared__ int s_col[128];

    const int tid  = threadIdx.x;
    const int lane = tid & 31;
    const int wid  = tid >> 5;
    const int wn   = wid & 3;        // 4 warps along n
    const int wm   = wid >> 2;       // 2 warps along m
    const int n_off = 32 * wn;
    const int m_off = 64 * wm;
    const int g = lane >> 2;         // 0..7
    const int t = lane & 3;          // 0..3

    if (tid < 128) { s_row[tid] = POSINF_BITS; s_col[tid] = POSINF_BITS; }

    float acc[2][8][4];
#pragma unroll
    for (int ta = 0; ta < 2; ta++)
#pragma unroll
        for (int tb = 0; tb < 8; tb++)
#pragma unroll
            for (int c = 0; c < 4; c++) acc[ta][tb][c] = 0.f;

    const int lrow = tid >> 2;           // 0..63
    const int lk   = (tid & 3) << 2;     // 0,4,8,12

    for (int kc = 0; kc < Dd; kc += 16) {
        __syncthreads();   // also orders s_row/s_col init before use
#pragma unroll
        for (int r = 0; r < 2; r++) {
            int row = lrow + 64 * r;
            float4 v = *(const float4*)(xb + (size_t)(n0 + row) * Dd + kc + lk);
            unsigned* xd = &Xs[row * SKX + lk];
            xd[0] = f2tf32(v.x); xd[1] = f2tf32(v.y);
            xd[2] = f2tf32(v.z); xd[3] = f2tf32(v.w);
            float4 w = *(const float4*)(yb + (size_t)(m0 + row) * Dd + kc + lk);
            unsigned* yd = &Ys[row * SKX + lk];
            yd[0] = f2tf32(w.x); yd[1] = f2tf32(w.y);
            yd[2] = f2tf32(w.z); yd[3] = f2tf32(w.w);
        }
        __syncthreads();
#pragma unroll
        for (int ks = 0; ks < 16; ks += 8) {
            unsigned af[2][4];
#pragma unroll
            for (int ta = 0; ta < 2; ta++) {
                int base = (n_off + 16 * ta + g) * SKX + ks + t;
                af[ta][0] = Xs[base];
                af[ta][1] = Xs[base + 8 * SKX];
                af[ta][2] = Xs[base + 4];
                af[ta][3] = Xs[base + 8 * SKX + 4];
            }
            unsigned bfr[8][2];
#pragma unroll
            for (int tb = 0; tb < 8; tb++) {
                int base = (m_off + 8 * tb + g) * SKX + ks + t;
                bfr[tb][0] = Ys[base];
                bfr[tb][1] = Ys[base + 4];
            }
#pragma unroll
            for (int ta = 0; ta < 2; ta++)
#pragma unroll
                for (int tb = 0; tb < 8; tb++)
                    mma_tf32(acc[ta][tb], af[ta], bfr[tb]);
        }
    }

    // epilogue: d = x2 + y2 - 2*S, fused row/col min
    // C fragment: c0:(g,2t) c1:(g,2t+1) c2:(g+8,2t) c3:(g+8,2t+1)
    const int nb = bf * Nn + n0, mb = bf * Nn + m0;
    float x2v[4];   // [ta*2+hi] -> n = n_off + 16ta + g + 8hi
#pragma unroll
    for (int ta = 0; ta < 2; ta++)
#pragma unroll
        for (int hi = 0; hi < 2; hi++)
            x2v[ta * 2 + hi] = g_x2[nb + n_off + 16 * ta + g + 8 * hi];
    float y2v[16];  // [tb*2+lo] -> m = m_off + 8tb + 2t + lo
#pragma unroll
    for (int tb = 0; tb < 8; tb++)
#pragma unroll
        for (int lo = 0; lo < 2; lo++)
            y2v[tb * 2 + lo] = g_y2[mb + m_off + 8 * tb + 2 * t + lo];

    const float INFF = __int_as_float(POSINF_BITS);
    float rmin[4], cmin[16];
#pragma unroll
    for (int i = 0; i < 4; i++) rmin[i] = INFF;
#pragma unroll
    for (int j = 0; j < 16; j++) cmin[j] = INFF;

#pragma unroll
    for (int ta = 0; ta < 2; ta++)
#pragma unroll
        for (int tb = 0; tb < 8; tb++)
#pragma unroll
            for (int hi = 0; hi < 2; hi++)
#pragma unroll
                for (int lo = 0; lo < 2; lo++) {
                    float s = acc[ta][tb][hi * 2 + lo];
                    float d = x2v[ta * 2 + hi] + y2v[tb * 2 + lo] - 2.f * s;
                    int ri = ta * 2 + hi, ci = tb * 2 + lo;
                    rmin[ri] = fminf(rmin[ri], d);
                    cmin[ci] = fminf(cmin[ci], d);
                }

#pragma unroll
    for (int ta = 0; ta < 2; ta++)
#pragma unroll
        for (int hi = 0; hi < 2; hi++)
            atomicMin(&s_row[n_off + 16 * ta + g + 8 * hi],
                      __float_as_int(rmin[ta * 2 + hi]));
#pragma unroll
    for (int tb = 0; tb < 8; tb++)
#pragma unroll
        for (int lo = 0; lo < 2; lo++)
            atomicMin(&s_col[m_off + 8 * tb + 2 * t + lo],
                      __float_as_int(cmin[tb * 2 + lo]));
    __syncthreads();
    if (tid < 128) {
        atomicMin(&g_rowmin[nb + tid], s_row[tid]);
        atomicMin(&g_colmin[mb + tid], s_col[tid]);
    }
}

// ---- reduce mins -> per-batch weights wx, wy ----
__global__ void k_wred() {
    int b = blockIdx.x;
    const int base = b * Ff * Nn;
    float sr = 0.f, sc = 0.f;
    for (int i = threadIdx.x; i < Ff * Nn; i += 256) {
        sr += __int_as_float(g_rowmin[base + i]);
        sc += __int_as_float(g_colmin[base + i]);
    }
    __shared__ float ssr[256], ssc[256];
    ssr[threadIdx.x] = sr; ssc[threadIdx.x] = sc;
    __syncthreads();
    for (int s = 128; s; s >>= 1) {
        if (threadIdx.x < s) {
            ssr[threadIdx.x] += ssr[threadIdx.x + s];
            ssc[threadIdx.x] += ssc[threadIdx.x + s];
        }
        __syncthreads();
    }
    if (threadIdx.x == 0) {
        g_wx[b] = 1.f / (1.f + ssr[0] / (float)(Ff * Nn));
        g_wy[b] = 1.f / (1.f + ssc[0] / (float)(Ff * Nn));
    }
}

// ---- per (bf,d) min/max over node dim, chunked over n ----
__global__ __launch_bounds__(256) void k_minmax(const float* __restrict__ x,
                                                const float* __restrict__ y) {
    int bf = blockIdx.x, c = blockIdx.y, d = threadIdx.x;
    const float* xp = x + ((size_t)bf * Nn + c * 128) * Dd + d;
    const float* yp = y + ((size_t)bf * Nn + c * 128) * Dd + d;
    const float INFF = __int_as_float(POSINF_BITS);
    float mnx = INFF, mxx = -INFF, mny = INFF, mxy = -INFF;
    for (int n = 0; n < 128; n++) {
        float vx = xp[(size_t)n * Dd];
        mnx = fminf(mnx, vx); mxx = fmaxf(mxx, vx);
        float vy = yp[(size_t)n * Dd];
        mny = fminf(mny, vy); mxy = fmaxf(mxy, vy);
    }
    int gi = bf * Dd + d;
    atomicMin(&g_mnx[gi], encf(mnx)); atomicMax(&g_mxx[gi], encf(mxx));
    atomicMin(&g_mny[gi], encf(mny)); atomicMax(&g_mxy[gi], encf(mxy));
}

// ---- fold weights + min/max into per-(bf,d) affine coefficients ----
__global__ void k_coef() {
    int i = blockIdx.x * blockDim.x + threadIdx.x;
    if (i >= BFD) return;
    int b = i / (Ff * Dd);
    float wx = g_wx[b], wy = g_wy[b];
    float mnx = decf(g_mnx[i]), mxx = decf(g_mxx[i]);
    float mny = decf(g_mny[i]), mxy = decf(g_mxy[i]);
    float sx = wx / (mxx - mnx);
    float sy = wy / (mxy - mny);
    g_sx[i] = sx; g_sy[i] = sy;
    g_of[i] = -mnx * sx - mny * sy;
}

// ---- final fused combine: out = x*sx + y*sy + off, float4 ----
__global__ __launch_bounds__(256) void k_combine(const float4* __restrict__ x,
                                                 const float4* __restrict__ y,
                                                 float4* __restrict__ out) {
    int idx = blockIdx.x * blockDim.x + threadIdx.x;
    const int total4 = Bb * Ff * Nn * Dd / 4;
    if (idx >= total4) return;
    int bf = idx / (Nn * Dd / 4);
    int d4 = idx & (Dd / 4 - 1);
    int ci = bf * (Dd / 4) + d4;
    float4 sx = ((const float4*)g_sx)[ci];
    float4 sy = ((const float4*)g_sy)[ci];
    float4 of = ((const float4*)g_of)[ci];
    float4 xv = x[idx], yv = y[idx];
    float4 o;
    o.x = fmaf(xv.x, sx.x, fmaf(yv.x, sy.x, of.x));
    o.y = fmaf(xv.y, sx.y, fmaf(yv.y, sy.y, of.y));
    o.z = fmaf(xv.z, sx.z, fmaf(yv.z, sy.z, of.z));
    o.w = fmaf(xv.w, sx.w, fmaf(yv.w, sy.w, of.w));
    out[idx] = o;
}

extern "C" void kernel_launch(void* const* d_in, const int* in_sizes, int n_in,
                              void* d_out, int out_size) {
    const float* x = (const float*)d_in[0];
    const float* y = (const float*)d_in[1];
    float* out = (float*)d_out;

    k_init<<<(BFN + 255) / 256, 256>>>();
    k_norms<<<BFN / 8, 256>>>(x, y);
    {
        dim3 gd(16 * 16, BFc);   // 256 tiles per frame, 20 frames
        k_dist<<<gd, 256>>>(x, y);
    }
    k_wred<<<Bb, 256>>>();
    {
        dim3 gm(BFc, Nn / 128);  // 20 frames x 16 n-chunks
        k_minmax<<<gm, 256>>>(x, y);
    }
    k_coef<<<(BFD + 255) / 256, 256>>>();
    {
        const int total4 = Bb * Ff * Nn * Dd / 4;
        k_combine<<<(total4 + 255) / 256, 256>>>((const float4*)x,
                                                 (const float4*)y,
                                                 (float4*)out);
    }
}

// round 13
// speedup vs baseline: 3.2927x; 1.5988x over previous
#include <cuda_runtime.h>

// Problem constants
#define Bb 4
#define Ff 5
#define Nn 2048
#define Dd 256
#define BFc (Bb*Ff)          // 20 frames
#define BFN (BFc*Nn)         // 40960
#define BFD (BFc*Dd)         // 5120
#define POSINF_BITS 0x7F800000

// ---- scratch (no allocations allowed -> device globals) ----
__device__ int      g_rowmin[BFN];   // float bits, min over m of d[n,m]
__device__ int      g_colmin[BFN];   // float bits, min over n of d[n,m]
__device__ float    g_x2[BFN];
__device__ float    g_y2[BFN];
__device__ unsigned g_mnx[BFD], g_mxx[BFD], g_mny[BFD], g_mxy[BFD];
__device__ float    g_wx[Bb], g_wy[Bb];
__device__ float    g_sx[BFD], g_sy[BFD], g_of[BFD];

// monotonic unsigned encoding of float (total order incl. negatives)
__device__ __forceinline__ unsigned encf(float f) {
    unsigned u = __float_as_uint(f);
    return (u & 0x80000000u) ? ~u : (u | 0x80000000u);
}
__device__ __forceinline__ float decf(unsigned e) {
    unsigned u = (e & 0x80000000u) ? (e ^ 0x80000000u) : ~e;
    return __uint_as_float(u);
}

// D(16x8,f32) += A(16x8,tf32,row) * B(8x8,tf32,col)
// Operands are raw fp32 bit patterns: HMMA.TF32 truncates low mantissa bits.
__device__ __forceinline__ void mma_tf32(float c[4],
                                         const unsigned a[4],
                                         const unsigned b[2]) {
    asm volatile(
        "mma.sync.aligned.m16n8k8.row.col.f32.tf32.tf32.f32 "
        "{%0,%1,%2,%3}, {%4,%5,%6,%7}, {%8,%9}, {%0,%1,%2,%3};"
        : "+f"(c[0]), "+f"(c[1]), "+f"(c[2]), "+f"(c[3])
        : "r"(a[0]), "r"(a[1]), "r"(a[2]), "r"(a[3]),
          "r"(b[0]), "r"(b[1]));
}

__device__ __forceinline__ void cpasync16(unsigned dst, const void* src) {
    asm volatile("cp.async.cg.shared.global [%0], [%1], 16;"
                 :: "r"(dst), "l"(src));
}
#define CP_COMMIT() asm volatile("cp.async.commit_group;" ::: "memory")
#define CP_WAIT0()  asm volatile("cp.async.wait_group 0;" ::: "memory")

// ---- reset accumulators (must run every launch: graph replays) ----
__global__ void k_init() {
    int i = blockIdx.x * blockDim.x + threadIdx.x;
    if (i < BFN) { g_rowmin[i] = POSINF_BITS; g_colmin[i] = POSINF_BITS; }
    if (i < BFD) {
        g_mnx[i] = 0xFFFFFFFFu; g_mny[i] = 0xFFFFFFFFu;
        g_mxx[i] = 0u;          g_mxy[i] = 0u;
    }
}

// ---- squared row norms: one warp per row, float4 loads ----
__global__ __launch_bounds__(256) void k_norms(const float* __restrict__ x,
                                               const float* __restrict__ y) {
    int row  = blockIdx.x * 8 + (threadIdx.x >> 5);
    int lane = threadIdx.x & 31;
    const float4* xr = (const float4*)(x + (size_t)row * Dd);
    const float4* yr = (const float4*)(y + (size_t)row * Dd);
    float sx = 0.f, sy = 0.f;
#pragma unroll
    for (int i = 0; i < 2; i++) {
        float4 v = xr[lane + 32 * i];
        sx += v.x * v.x + v.y * v.y + v.z * v.z + v.w * v.w;
        float4 w = yr[lane + 32 * i];
        sy += w.x * w.x + w.y * w.y + w.z * w.z + w.w * w.w;
    }
#pragma unroll
    for (int o = 16; o; o >>= 1) {
        sx += __shfl_xor_sync(0xFFFFFFFFu, sx, o);
        sy += __shfl_xor_sync(0xFFFFFFFFu, sy, o);
    }
    if (lane == 0) { g_x2[row] = sx; g_y2[row] = sy; }
}

// ---- tensor-core distance kernel, cp.async double-buffered ----
// 128x128 CTA tile, 8 warps: warp = 32(n) x 64(m) = 2 x 8 m16n8k8 MMA tiles.
// Raw fp32 bits fed to tf32 MMA (HW truncation). Epilogue fuses
// d = x2+y2-2S with row/col min reductions.
#define SKX 20                    // smem row stride in floats (16 + 4 pad)
#define STAGE_U (128 * SKX)       // per-tensor stage size (unsigned words)
__global__ __launch_bounds__(256, 2) void k_dist(const float* __restrict__ x,
                                                 const float* __restrict__ y) {
    const int bf = blockIdx.y;
    const int nt = blockIdx.x >> 4;
    const int mt = blockIdx.x & 15;
    const int n0 = nt * 128, m0 = mt * 128;
    const float* xb = x + (size_t)bf * Nn * Dd;
    const float* yb = y + (size_t)bf * Nn * Dd;

    __shared__ unsigned Xs[2][STAGE_U];   // fp32 bits, [n][k]
    __shared__ unsigned Ys[2][STAGE_U];   // fp32 bits, [m][k]
    __shared__ int s_row[128];
    __shared__ int s_col[128];

    const int tid  = threadIdx.x;
    const int lane = tid & 31;
    const int wid  = tid >> 5;
    const int n_off = 32 * (wid & 3);
    const int m_off = 64 * (wid >> 2);
    const int g = lane >> 2;         // 0..7
    const int t = lane & 3;          // 0..3

    if (tid < 128) { s_row[tid] = POSINF_BITS; s_col[tid] = POSINF_BITS; }

    float acc[2][8][4];
#pragma unroll
    for (int ta = 0; ta < 2; ta++)
#pragma unroll
        for (int tb = 0; tb < 8; tb++)
#pragma unroll
            for (int c = 0; c < 4; c++) acc[ta][tb][c] = 0.f;

    // cp.async fill geometry: 512 16B-chunks per tensor per stage,
    // thread covers chunks tid and tid+256. chunk c -> row c>>2, kpart c&3.
    const int frow = tid >> 2;          // 0..63
    const int fkp  = tid & 3;           // 0..3
    unsigned xs_base = (unsigned)__cvta_generic_to_shared(&Xs[0][0]);
    unsigned ys_base = (unsigned)__cvta_generic_to_shared(&Ys[0][0]);
    const unsigned dst_off = (unsigned)frow * (SKX * 4) + (unsigned)fkp * 16;

#define FILL(st, kc)                                                          \
    do {                                                                      \
        unsigned xd = xs_base + (st) * (STAGE_U * 4) + dst_off;               \
        unsigned yd = ys_base + (st) * (STAGE_U * 4) + dst_off;               \
        const float* xs0 = xb + (size_t)(n0 + frow) * Dd + (kc) + fkp * 4;    \
        const float* ys0 = yb + (size_t)(m0 + frow) * Dd + (kc) + fkp * 4;    \
        cpasync16(xd, xs0);                                                   \
        cpasync16(xd + 64 * (SKX * 4), xs0 + (size_t)64 * Dd);                \
        cpasync16(yd, ys0);                                                   \
        cpasync16(yd + 64 * (SKX * 4), ys0 + (size_t)64 * Dd);                \
    } while (0)

    FILL(0, 0);
    CP_COMMIT();
    CP_WAIT0();
    __syncthreads();

    for (int i = 0; i < 16; i++) {
        // prefetch next chunk into the other buffer (its previous contents
        // were consumed at iteration i-1, fenced by the sync that admitted us)
        if (i + 1 < 16) {
            FILL((i + 1) & 1, (i + 1) * 16);
            CP_COMMIT();
        }
        const unsigned* Xc = &Xs[i & 1][0];
        const unsigned* Yc = &Ys[i & 1][0];
#pragma unroll
        for (int ks = 0; ks < 16; ks += 8) {
            unsigned af[2][4];
#pragma unroll
            for (int ta = 0; ta < 2; ta++) {
                int base = (n_off + 16 * ta + g) * SKX + ks + t;
                af[ta][0] = Xc[base];
                af[ta][1] = Xc[base + 8 * SKX];
                af[ta][2] = Xc[base + 4];
                af[ta][3] = Xc[base + 8 * SKX + 4];
            }
            unsigned bfr[8][2];
#pragma unroll
            for (int tb = 0; tb < 8; tb++) {
                int base = (m_off + 8 * tb + g) * SKX + ks + t;
                bfr[tb][0] = Yc[base];
                bfr[tb][1] = Yc[base + 4];
            }
#pragma unroll
            for (int ta = 0; ta < 2; ta++)
#pragma unroll
                for (int tb = 0; tb < 8; tb++)
                    mma_tf32(acc[ta][tb], af[ta], bfr[tb]);
        }
        if (i + 1 < 16) {
            CP_WAIT0();        // next stage landed (overlapped with MMAs above)
            __syncthreads();   // all threads' chunks visible; gates buf reuse
        }
    }

    // epilogue: d = x2 + y2 - 2*S, fused row/col min
    // C fragment: c0:(g,2t) c1:(g,2t+1) c2:(g+8,2t) c3:(g+8,2t+1)
    const int nb = bf * Nn + n0, mb = bf * Nn + m0;
    float x2v[4];
#pragma unroll
    for (int ta = 0; ta < 2; ta++)
#pragma unroll
        for (int hi = 0; hi < 2; hi++)
            x2v[ta * 2 + hi] = g_x2[nb + n_off + 16 * ta + g + 8 * hi];
    float y2v[16];
#pragma unroll
    for (int tb = 0; tb < 8; tb++)
#pragma unroll
        for (int lo = 0; lo < 2; lo++)
            y2v[tb * 2 + lo] = g_y2[mb + m_off + 8 * tb + 2 * t + lo];

    const float INFF = __int_as_float(POSINF_BITS);
    float rmin[4], cmin[16];
#pragma unroll
    for (int i = 0; i < 4; i++) rmin[i] = INFF;
#pragma unroll
    for (int j = 0; j < 16; j++) cmin[j] = INFF;

#pragma unroll
    for (int ta = 0; ta < 2; ta++)
#pragma unroll
        for (int tb = 0; tb < 8; tb++)
#pragma unroll
            for (int hi = 0; hi < 2; hi++)
#pragma unroll
                for (int lo = 0; lo < 2; lo++) {
                    float s = acc[ta][tb][hi * 2 + lo];
                    float d = x2v[ta * 2 + hi] + y2v[tb * 2 + lo] - 2.f * s;
                    int ri = ta * 2 + hi, ci = tb * 2 + lo;
                    rmin[ri] = fminf(rmin[ri], d);
                    cmin[ci] = fminf(cmin[ci], d);
                }

    __syncthreads();   // s_row/s_col init (tid<128) already done far earlier;
                       // this orders last compute-buffer reads before reuse-free exit
#pragma unroll
    for (int ta = 0; ta < 2; ta++)
#pragma unroll
        for (int hi = 0; hi < 2; hi++)
            atomicMin(&s_row[n_off + 16 * ta + g + 8 * hi],
                      __float_as_int(rmin[ta * 2 + hi]));
#pragma unroll
    for (int tb = 0; tb < 8; tb++)
#pragma unroll
        for (int lo = 0; lo < 2; lo++)
            atomicMin(&s_col[m_off + 8 * tb + 2 * t + lo],
                      __float_as_int(cmin[tb * 2 + lo]));
    __syncthreads();
    if (tid < 128) {
        atomicMin(&g_rowmin[nb + tid], s_row[tid]);
        atomicMin(&g_colmin[mb + tid], s_col[tid]);
    }
#undef FILL
}

// ---- reduce mins -> per-batch weights wx, wy ----
__global__ void k_wred() {
    int b = blockIdx.x;
    const int base = b * Ff * Nn;
    float sr = 0.f, sc = 0.f;
    for (int i = threadIdx.x; i < Ff * Nn; i += 256) {
        sr += __int_as_float(g_rowmin[base + i]);
        sc += __int_as_float(g_colmin[base + i]);
    }
    __shared__ float ssr[256], ssc[256];
    ssr[threadIdx.x] = sr; ssc[threadIdx.x] = sc;
    __syncthreads();
    for (int s = 128; s; s >>= 1) {
        if (threadIdx.x < s) {
            ssr[threadIdx.x] += ssr[threadIdx.x + s];
            ssc[threadIdx.x] += ssc[threadIdx.x + s];
        }
        __syncthreads();
    }
    if (threadIdx.x == 0) {
        g_wx[b] = 1.f / (1.f + ssr[0] / (float)(Ff * Nn));
        g_wy[b] = 1.f / (1.f + ssc[0] / (float)(Ff * Nn));
    }
}

// ---- per (bf,d) min/max over node dim, chunked over n ----
__global__ __launch_bounds__(256) void k_minmax(const float* __restrict__ x,
                                                const float* __restrict__ y) {
    int bf = blockIdx.x, c = blockIdx.y, d = threadIdx.x;
    const float* xp = x + ((size_t)bf * Nn + c * 128) * Dd + d;
    const float* yp = y + ((size_t)bf * Nn + c * 128) * Dd + d;
    const float INFF = __int_as_float(POSINF_BITS);
    float mnx = INFF, mxx = -INFF, mny = INFF, mxy = -INFF;
    for (int n = 0; n < 128; n++) {
        float vx = xp[(size_t)n * Dd];
        mnx = fminf(mnx, vx); mxx = fmaxf(mxx, vx);
        float vy = yp[(size_t)n * Dd];
        mny = fminf(mny, vy); mxy = fmaxf(mxy, vy);
    }
    int gi = bf * Dd + d;
    atomicMin(&g_mnx[gi], encf(mnx)); atomicMax(&g_mxx[gi], encf(mxx));
    atomicMin(&g_mny[gi], encf(mny)); atomicMax(&g_mxy[gi], encf(mxy));
}

// ---- fold weights + min/max into per-(bf,d) affine coefficients ----
__global__ void k_coef() {
    int i = blockIdx.x * blockDim.x + threadIdx.x;
    if (i >= BFD) return;
    int b = i / (Ff * Dd);
    float wx = g_wx[b], wy = g_wy[b];
    float mnx = decf(g_mnx[i]), mxx = decf(g_mxx[i]);
    float mny = decf(g_mny[i]), mxy = decf(g_mxy[i]);
    float sx = wx / (mxx - mnx);
    float sy = wy / (mxy - mny);
    g_sx[i] = sx; g_sy[i] = sy;
    g_of[i] = -mnx * sx - mny * sy;
}

// ---- final fused combine: out = x*sx + y*sy + off, float4 ----
__global__ __launch_bounds__(256) void k_combine(const float4* __restrict__ x,
                                                 const float4* __restrict__ y,
                                                 float4* __restrict__ out) {
    int idx = blockIdx.x * blockDim.x + threadIdx.x;
    const int total4 = Bb * Ff * Nn * Dd / 4;
    if (idx >= total4) return;
    int bf = idx / (Nn * Dd / 4);
    int d4 = idx & (Dd / 4 - 1);
    int ci = bf * (Dd / 4) + d4;
    float4 sx = ((const float4*)g_sx)[ci];
    float4 sy = ((const float4*)g_sy)[ci];
    float4 of = ((const float4*)g_of)[ci];
    float4 xv = x[idx], yv = y[idx];
    float4 o;
    o.x = fmaf(xv.x, sx.x, fmaf(yv.x, sy.x, of.x));
    o.y = fmaf(xv.y, sx.y, fmaf(yv.y, sy.y, of.y));
    o.z = fmaf(xv.z, sx.z, fmaf(yv.z, sy.z, of.z));
    o.w = fmaf(xv.w, sx.w, fmaf(yv.w, sy.w, of.w));
    out[idx] = o;
}

extern "C" void kernel_launch(void* const* d_in, const int* in_sizes, int n_in,
                              void* d_out, int out_size) {
    const float* x = (const float*)d_in[0];
    const float* y = (const float*)d_in[1];
    float* out = (float*)d_out;

    k_init<<<(BFN + 255) / 256, 256>>>();
    k_norms<<<BFN / 8, 256>>>(x, y);
    {
        dim3 gd(16 * 16, BFc);   // 256 tiles per frame, 20 frames
        k_dist<<<gd, 256>>>(x, y);
    }
    k_wred<<<Bb, 256>>>();
    {
        dim3 gm(BFc, Nn / 128);  // 20 frames x 16 n-chunks
        k_minmax<<<gm, 256>>>(x, y);
    }
    k_coef<<<(BFD + 255) / 256, 256>>>();
    {
        const int total4 = Bb * Ff * Nn * Dd / 4;
        k_combine<<<(total4 + 255) / 256, 256>>>((const float4*)x,
                                                 (const float4*)y,
                                                 (float4*)out);
    }
}